// round 6
// baseline (speedup 1.0000x reference)
#include <cuda_runtime.h>
#include <cuda_bf16.h>
#include <math.h>
#include <float.h>
#include <stdint.h>

#define NN 50000
#define NE 800000
#define NHEAD 4

// ---------------- scratch (device globals; no allocation allowed) ----------------
__device__ float g_z[(size_t)NN * 256];    // GEMM0/1 output (projected feats, fp32)
__device__ float g_h[(size_t)NN * 256];    // hidden activations (fp32, for scores/agg)
__device__ __nv_bfloat16 g_ahi[(size_t)NN * 1024];  // GEMM A operand, bf16 high part
__device__ __nv_bfloat16 g_alo[(size_t)NN * 1024];  // GEMM A operand, bf16 low part
__device__ __nv_bfloat16 g_bthi[256 * 1024];        // GEMM B operand [N,K] K-major, hi
__device__ __nv_bfloat16 g_btlo[256 * 1024];        // GEMM B operand [N,K] K-major, lo
__device__ float g_el[NN * NHEAD];
__device__ float g_er[NN * NHEAD];
__device__ float g_alpha[(size_t)NE * NHEAD];  // normalized attention, dst-sorted order
__device__ int   g_ss[NE];                     // src node per sorted edge
__device__ int   g_deg[NN];
__device__ int   g_cur[NN];
__device__ int   g_off[NN + 1];
__device__ float g_wl2[NHEAD * 256];
__device__ float g_wr2[NHEAD * 256];
__device__ float g_bias2[256];

// ================= warp-MMA helpers (sm_80+ PTX, works under compute_103) =================
__device__ __forceinline__ uint32_t smem_u32(const void* p) {
    uint32_t a;
    asm("{ .reg .u64 t; cvta.to.shared.u64 t, %1; cvt.u32.u64 %0, t; }" : "=r"(a) : "l"(p));
    return a;
}
#define LDM4(r0, r1, r2, r3, addr) \
    asm volatile("ldmatrix.sync.aligned.m8n8.x4.shared.b16 {%0,%1,%2,%3}, [%4];" \
                 : "=r"(r0), "=r"(r1), "=r"(r2), "=r"(r3) : "r"(addr))
#define MMA16816(d, a, b) \
    asm volatile("mma.sync.aligned.m16n8k16.row.col.f32.bf16.bf16.f32 " \
                 "{%0,%1,%2,%3}, {%4,%5,%6,%7}, {%8,%9}, {%0,%1,%2,%3};" \
                 : "+f"((d)[0]), "+f"((d)[1]), "+f"((d)[2]), "+f"((d)[3]) \
                 : "r"((a)[0]), "r"((a)[1]), "r"((a)[2]), "r"((a)[3]), \
                   "r"((b)[0]), "r"((b)[1]))
#define CP_ASYNC16(daddr, sptr) \
    asm volatile("cp.async.cg.shared.global [%0], [%1], 16;" :: "r"(daddr), "l"(sptr))
#define CP_COMMIT() asm volatile("cp.async.commit_group;" ::: "memory")
#define CP_WAIT1() asm volatile("cp.async.wait_group 1;" ::: "memory")
#define CP_WAIT0() asm volatile("cp.async.wait_group 0;" ::: "memory")

// ================= split-bf16 tensor-core GEMM, 2-stage cp.async pipeline =================
// C[M,N] = scale*(A@B^T) + bias.  A=[M,K] K-major bf16 hi/lo, B=[N,K] K-major bf16 hi/lo.
// Block 128x128, BK=32, 8 warps of 64x32. N multiple of 128, K multiple of 32, M guarded.
#define GBM 128
#define GBN 128
#define GBK 32
#define GPAD 40
#define TILE_ELEMS (128 * GPAD)
#define STAGE_ELEMS (4 * TILE_ELEMS)
#define GEMM_SMEM (2 * STAGE_ELEMS * 2)   // bytes

__device__ __forceinline__ void g2s_stage(
    __nv_bfloat16* sbase,
    const __nv_bfloat16* __restrict__ Ahi, const __nv_bfloat16* __restrict__ Alo,
    const __nv_bfloat16* __restrict__ Bhi, const __nv_bfloat16* __restrict__ Blo,
    int bm, int bn, int M, int K, int k0, int tid) {
#pragma unroll
    for (int t = 0; t < 8; t++) {
        int idx = tid + t * 256;
        int tile = idx >> 9;        // 0:Ahi 1:Alo 2:Bhi 3:Blo
        int u = idx & 511;
        int row = u >> 2;
        int ch = u & 3;
        __nv_bfloat16* d = sbase + tile * TILE_ELEMS + row * GPAD + ch * 8;
        if (tile < 2) {
            int gm = bm + row;
            if (gm < M) {
                const __nv_bfloat16* s = (tile == 0 ? Ahi : Alo) + (size_t)gm * K + k0 + ch * 8;
                CP_ASYNC16(smem_u32(d), s);
            } else {
                *reinterpret_cast<uint4*>(d) = make_uint4(0, 0, 0, 0);
            }
        } else {
            int gn = bn + row;
            const __nv_bfloat16* s = (tile == 2 ? Bhi : Blo) + (size_t)gn * K + k0 + ch * 8;
            CP_ASYNC16(smem_u32(d), s);
        }
    }
}

__global__ void __launch_bounds__(256)
k_gemm_mma(const __nv_bfloat16* __restrict__ Ahi, const __nv_bfloat16* __restrict__ Alo,
           const __nv_bfloat16* __restrict__ Bhi, const __nv_bfloat16* __restrict__ Blo,
           float* __restrict__ C, int M, int N, int K,
           float scale, const float* __restrict__ bias) {
    extern __shared__ __nv_bfloat16 smem[];

    int tid = threadIdx.x;
    int lane = tid & 31;
    int wid = tid >> 5;
    int wm = wid >> 2;   // 0..1 -> 64-row block
    int wn = wid & 3;    // 0..3 -> 32-col block
    int bm = blockIdx.y * GBM;
    int bn = blockIdx.x * GBN;

    float acc[4][4][4];
#pragma unroll
    for (int i = 0; i < 4; i++)
#pragma unroll
        for (int j = 0; j < 4; j++)
#pragma unroll
            for (int r = 0; r < 4; r++) acc[i][j][r] = 0.f;

    int lrow = lane & 15;            // ldmatrix row within 16
    int lcol = (lane >> 4) * 8;      // ldmatrix col-half

    int nst = K / GBK;
    // prologue: prefetch stage 0
    g2s_stage(smem, Ahi, Alo, Bhi, Blo, bm, bn, M, K, 0, tid);
    CP_COMMIT();

    for (int s = 0; s < nst; s++) {
        if (s + 1 < nst) {
            g2s_stage(smem + ((s + 1) & 1) * STAGE_ELEMS, Ahi, Alo, Bhi, Blo,
                      bm, bn, M, K, (s + 1) * GBK, tid);
            CP_COMMIT();
            CP_WAIT1();
        } else {
            CP_WAIT0();
        }
        __syncthreads();

        __nv_bfloat16* buf = smem + (s & 1) * STAGE_ELEMS;
        uint32_t bAhi = smem_u32(buf);
        uint32_t bAlo = smem_u32(buf + TILE_ELEMS);
        uint32_t bBhi = smem_u32(buf + 2 * TILE_ELEMS);
        uint32_t bBlo = smem_u32(buf + 3 * TILE_ELEMS);

#pragma unroll
        for (int kk = 0; kk < 2; kk++) {
            int kb = kk * 16;
            uint32_t ahi[4][4], alo[4][4];
#pragma unroll
            for (int i = 0; i < 4; i++) {
                uint32_t off = (uint32_t)((wm * 64 + i * 16 + lrow) * GPAD + kb + lcol) * 2;
                LDM4(ahi[i][0], ahi[i][1], ahi[i][2], ahi[i][3], bAhi + off);
                LDM4(alo[i][0], alo[i][1], alo[i][2], alo[i][3], bAlo + off);
            }
            uint32_t bhi[4][2], blo[4][2];
#pragma unroll
            for (int j = 0; j < 2; j++) {
                uint32_t off = (uint32_t)((wn * 32 + j * 16 + lrow) * GPAD + kb + lcol) * 2;
                uint32_t r0, r1, r2, r3;
                LDM4(r0, r1, r2, r3, bBhi + off);
                bhi[2 * j][0] = r0; bhi[2 * j][1] = r2;
                bhi[2 * j + 1][0] = r1; bhi[2 * j + 1][1] = r3;
                LDM4(r0, r1, r2, r3, bBlo + off);
                blo[2 * j][0] = r0; blo[2 * j][1] = r2;
                blo[2 * j + 1][0] = r1; blo[2 * j + 1][1] = r3;
            }
#pragma unroll
            for (int i = 0; i < 4; i++)
#pragma unroll
                for (int n = 0; n < 4; n++) {
                    MMA16816(acc[i][n], ahi[i], bhi[n]);
                    MMA16816(acc[i][n], ahi[i], blo[n]);
                    MMA16816(acc[i][n], alo[i], bhi[n]);
                }
        }
        __syncthreads();
    }

    // ---- epilogue: documented m16n8 acc mapping, guarded direct global stores
    int g = lane >> 2, tg = lane & 3;
#pragma unroll
    for (int mi = 0; mi < 4; mi++) {
        int r0 = bm + wm * 64 + mi * 16 + g;
        int r1 = r0 + 8;
#pragma unroll
        for (int ni = 0; ni < 4; ni++) {
            int c = bn + wn * 32 + ni * 8 + tg * 2;
            float b0 = 0.f, b1 = 0.f;
            if (bias) { b0 = bias[c]; b1 = bias[c + 1]; }
            if (r0 < M) {
                float2 v = make_float2(scale * acc[mi][ni][0] + b0,
                                       scale * acc[mi][ni][1] + b1);
                *reinterpret_cast<float2*>(&C[(size_t)r0 * N + c]) = v;
            }
            if (r1 < M) {
                float2 v = make_float2(scale * acc[mi][ni][2] + b0,
                                       scale * acc[mi][ni][3] + b1);
                *reinterpret_cast<float2*>(&C[(size_t)r1 * N + c]) = v;
            }
        }
    }
}

// ================= bf16 split conversions =================
__global__ void k_splitA(const float* __restrict__ in, __nv_bfloat16* __restrict__ hi,
                         __nv_bfloat16* __restrict__ lo, int count) {
    int i = blockIdx.x * blockDim.x + threadIdx.x;
    if (i >= count) return;
    float f = in[i];
    __nv_bfloat16 h = __float2bfloat16(f);
    hi[i] = h;
    lo[i] = __float2bfloat16(f - __bfloat162float(h));
}

// transpose W[K,N] -> Wt[N,K] with split
__global__ void k_splitWt(const float* __restrict__ W, int K, int N) {
    int t = blockIdx.x * blockDim.x + threadIdx.x;
    if (t >= K * N) return;
    int n = t / K, k = t % K;
    float f = W[(size_t)k * N + n];
    __nv_bfloat16 h = __float2bfloat16(f);
    g_bthi[t] = h;
    g_btlo[t] = __float2bfloat16(f - __bfloat162float(h));
}

// layer2 B: Bt[c][h*256+kk] = W2[kk*1024 + h*256 + c], output [256,1024]
__global__ void k_splitW2(const float* __restrict__ W2) {
    int t = blockIdx.x * blockDim.x + threadIdx.x;   // 0..262143
    if (t >= 256 * 1024) return;
    int c = t >> 10;
    int r = t & 1023;
    int h = r >> 8, kk = r & 255;
    float f = W2[(size_t)kk * 1024 + h * 256 + c];
    __nv_bfloat16 hh = __float2bfloat16(f);
    g_bthi[t] = hh;
    g_btlo[t] = __float2bfloat16(f - __bfloat162float(hh));
}

// ---------------- CSR build (by destination) ----------------
__global__ void k_zero_deg() {
    int i = blockIdx.x * blockDim.x + threadIdx.x;
    if (i < NN) g_deg[i] = 0;
}
__global__ void k_count(const int* __restrict__ dst) {
    int i = blockIdx.x * blockDim.x + threadIdx.x;
    if (i < NE) atomicAdd(&g_deg[dst[i]], 1);
}
__global__ void k_scan() {
    __shared__ int sh[1024];
    __shared__ int carry;
    if (threadIdx.x == 0) carry = 0;
    __syncthreads();
    for (int base = 0; base < NN; base += 1024) {
        int i = base + threadIdx.x;
        int v = (i < NN) ? g_deg[i] : 0;
        sh[threadIdx.x] = v;
        __syncthreads();
        for (int o = 1; o < 1024; o <<= 1) {
            int t = (threadIdx.x >= o) ? sh[threadIdx.x - o] : 0;
            __syncthreads();
            sh[threadIdx.x] += t;
            __syncthreads();
        }
        if (i < NN) {
            int excl = carry + sh[threadIdx.x] - v;
            g_off[i] = excl;
            g_cur[i] = excl;
        }
        __syncthreads();
        if (threadIdx.x == 0) carry += sh[1023];
        __syncthreads();
    }
    if (threadIdx.x == 0) g_off[NN] = carry;
}
// fill: writes src id directly into dst-sorted slot (g_eidx eliminated)
__global__ void k_fill(const int* __restrict__ src, const int* __restrict__ dst) {
    int i = blockIdx.x * blockDim.x + threadIdx.x;
    if (i < NE) {
        int d = dst[i];
        int p = atomicAdd(&g_cur[d], 1);
        g_ss[p] = src[i];
    }
}

// ---------------- layer-2 precompute ----------------
__global__ void k_prep_scores(const float* __restrict__ W2, const float* __restrict__ al2,
                              const float* __restrict__ ar2) {
    int t = blockIdx.x * blockDim.x + threadIdx.x;
    int which = t >> 10;
    int hk = t & 1023;
    int h = hk >> 8, k = hk & 255;
    const float* a = (which == 0 ? al2 : ar2) + h * 256;
    const float* wrow = W2 + (size_t)k * 1024 + h * 256;
    float s = 0.f;
#pragma unroll 8
    for (int c = 0; c < 256; c++) s += wrow[c] * a[c];
    if (which == 0) g_wl2[hk] = s;
    else            g_wr2[hk] = s;
}
__global__ void k_bias2(const float* __restrict__ b2) {
    int c = threadIdx.x;
    g_bias2[c] = 0.25f * (b2[c] + b2[256 + c] + b2[512 + c] + b2[768 + c]);
}

// ---------------- per-node attention scores (layers 0/1, F=64) ----------------
__global__ void k_scores(const float* __restrict__ z, const float* __restrict__ al,
                         const float* __restrict__ ar) {
    int gw = (blockIdx.x * blockDim.x + threadIdx.x) >> 5;
    int lane = threadIdx.x & 31;
    if (gw >= NN) return;
    const float* row = z + (size_t)gw * 256;
    float accl[NHEAD], accr[NHEAD];
#pragma unroll
    for (int h = 0; h < NHEAD; h++) { accl[h] = 0.f; accr[h] = 0.f; }
#pragma unroll
    for (int i = 0; i < 8; i++) {
        int j = lane + 32 * i;
        float v = row[j];
        int h = i >> 1;
        accl[h] += v * al[j];
        accr[h] += v * ar[j];
    }
#pragma unroll
    for (int h = 0; h < NHEAD; h++) {
        float l = accl[h], r = accr[h];
#pragma unroll
        for (int o = 16; o > 0; o >>= 1) {
            l += __shfl_xor_sync(0xffffffffu, l, o);
            r += __shfl_xor_sync(0xffffffffu, r, o);
        }
        if (lane == 0) {
            g_el[gw * NHEAD + h] = l;
            g_er[gw * NHEAD + h] = r;
        }
    }
}

// ---------------- layer-2 scores directly from h1 ----------------
__global__ void k_scores2(const float* __restrict__ h1) {
    int gw = (blockIdx.x * blockDim.x + threadIdx.x) >> 5;
    int lane = threadIdx.x & 31;
    if (gw >= NN) return;
    const float* row = h1 + (size_t)gw * 256;
    float accl[NHEAD], accr[NHEAD];
#pragma unroll
    for (int h = 0; h < NHEAD; h++) { accl[h] = 0.f; accr[h] = 0.f; }
#pragma unroll
    for (int i = 0; i < 8; i++) {
        int j = lane + 32 * i;
        float v = row[j];
#pragma unroll
        for (int h = 0; h < NHEAD; h++) {
            accl[h] += v * g_wl2[h * 256 + j];
            accr[h] += v * g_wr2[h * 256 + j];
        }
    }
#pragma unroll
    for (int h = 0; h < NHEAD; h++) {
        float l = accl[h], r = accr[h];
#pragma unroll
        for (int o = 16; o > 0; o >>= 1) {
            l += __shfl_xor_sync(0xffffffffu, l, o);
            r += __shfl_xor_sync(0xffffffffu, r, o);
        }
        if (lane == 0) {
            g_el[gw * NHEAD + h] = l;
            g_er[gw * NHEAD + h] = r;
        }
    }
}

// ---------------- per-node segment softmax (scores computed on the fly) ----------------
__device__ __forceinline__ float4 edge_score(int s, const float4& er) {
    float4 l = *reinterpret_cast<const float4*>(&g_el[s * 4]);
    float4 v;
    float x;
    x = l.x + er.x; v.x = x > 0.f ? x : 0.2f * x;
    x = l.y + er.y; v.y = x > 0.f ? x : 0.2f * x;
    x = l.z + er.z; v.z = x > 0.f ? x : 0.2f * x;
    x = l.w + er.w; v.w = x > 0.f ? x : 0.2f * x;
    return v;
}

__global__ void k_stats() {
    int n = (blockIdx.x * blockDim.x + threadIdx.x) >> 5;
    int lane = threadIdx.x & 31;
    if (n >= NN) return;
    int j0 = g_off[n], j1 = g_off[n + 1];
    float4 er = *reinterpret_cast<const float4*>(&g_er[n * 4]);
    float m[NHEAD], s[NHEAD];
#pragma unroll
    for (int h = 0; h < NHEAD; h++) { m[h] = -FLT_MAX; s[h] = 0.f; }
    for (int j = j0 + lane; j < j1; j += 32) {
        float4 e4 = edge_score(g_ss[j], er);
        float ev[4] = {e4.x, e4.y, e4.z, e4.w};
#pragma unroll
        for (int h = 0; h < NHEAD; h++) {
            float nm = fmaxf(m[h], ev[h]);
            s[h] = s[h] * __expf(m[h] - nm) + __expf(ev[h] - nm);
            m[h] = nm;
        }
    }
#pragma unroll
    for (int h = 0; h < NHEAD; h++) {
#pragma unroll
        for (int o = 16; o > 0; o >>= 1) {
            float om = __shfl_xor_sync(0xffffffffu, m[h], o);
            float os = __shfl_xor_sync(0xffffffffu, s[h], o);
            float nm = fmaxf(m[h], om);
            s[h] = s[h] * __expf(m[h] - nm) + os * __expf(om - nm);
            m[h] = nm;
        }
    }
    float inv[NHEAD];
#pragma unroll
    for (int h = 0; h < NHEAD; h++) inv[h] = 1.f / fmaxf(s[h], 1e-9f);
    for (int j = j0 + lane; j < j1; j += 32) {
        float4 e4 = edge_score(g_ss[j], er);
        float4 a;
        a.x = __expf(e4.x - m[0]) * inv[0];
        a.y = __expf(e4.y - m[1]) * inv[1];
        a.z = __expf(e4.z - m[2]) * inv[2];
        a.w = __expf(e4.w - m[3]) * inv[3];
        *reinterpret_cast<float4*>(&g_alpha[(size_t)j * 4]) = a;
    }
}

// ---------------- hidden-layer aggregation: warp per node, all 4 heads ----------------
// writes fp32 h and bf16 hi/lo split (as next GEMM's A operand, K=256)
__global__ void k_agg_mid(const float* __restrict__ z, const float* __restrict__ bias,
                          float* __restrict__ hout) {
    int n = (blockIdx.x * blockDim.x + threadIdx.x) >> 5;
    int lane = threadIdx.x & 31;
    if (n >= NN) return;
    int j0 = g_off[n], j1 = g_off[n + 1];
    float acc[NHEAD][2];
#pragma unroll
    for (int h = 0; h < NHEAD; h++) { acc[h][0] = 0.f; acc[h][1] = 0.f; }
    for (int j = j0; j < j1; j++) {
        float4 a = *reinterpret_cast<const float4*>(&g_alpha[(size_t)j * 4]);
        const float* zr = z + (size_t)g_ss[j] * 256;
        float av[4] = {a.x, a.y, a.z, a.w};
#pragma unroll
        for (int h = 0; h < NHEAD; h++) {
            acc[h][0] += av[h] * zr[h * 64 + lane];
            acc[h][1] += av[h] * zr[h * 64 + lane + 32];
        }
    }
#pragma unroll
    for (int h = 0; h < NHEAD; h++) {
        float v0 = acc[h][0] + bias[h * 64 + lane];
        float v1 = acc[h][1] + bias[h * 64 + lane + 32];
        v0 = v0 > 0.f ? v0 : (__expf(v0) - 1.f);
        v1 = v1 > 0.f ? v1 : (__expf(v1) - 1.f);
        size_t i0 = (size_t)n * 256 + h * 64 + lane;
        hout[i0] = v0;
        hout[i0 + 32] = v1;
        __nv_bfloat16 h0 = __float2bfloat16(v0);
        __nv_bfloat16 h1b = __float2bfloat16(v1);
        g_ahi[i0] = h0;
        g_ahi[i0 + 32] = h1b;
        g_alo[i0] = __float2bfloat16(v0 - __bfloat162float(h0));
        g_alo[i0 + 32] = __float2bfloat16(v1 - __bfloat162float(h1b));
    }
}

// ---------------- layer-2 aggregation of h1 into bf16 split A [N,1024] ----------------
__global__ void k_agg2(const float* __restrict__ h1) {
    int n = (blockIdx.x * blockDim.x + threadIdx.x) >> 5;
    int lane = threadIdx.x & 31;
    if (n >= NN) return;
    int j0 = g_off[n], j1 = g_off[n + 1];
    float acc[NHEAD][8];
#pragma unroll
    for (int h = 0; h < NHEAD; h++)
#pragma unroll
        for (int p = 0; p < 8; p++) acc[h][p] = 0.f;
    for (int j = j0; j < j1; j++) {
        float4 a = *reinterpret_cast<const float4*>(&g_alpha[(size_t)j * 4]);
        const float* hr = h1 + (size_t)g_ss[j] * 256;
#pragma unroll
        for (int p = 0; p < 8; p++) {
            float v = hr[lane + 32 * p];
            acc[0][p] += a.x * v;
            acc[1][p] += a.y * v;
            acc[2][p] += a.z * v;
            acc[3][p] += a.w * v;
        }
    }
    size_t base = (size_t)n * 1024;
#pragma unroll
    for (int h = 0; h < NHEAD; h++)
#pragma unroll
        for (int p = 0; p < 8; p++) {
            float v = acc[h][p];
            size_t idx = base + h * 256 + lane + 32 * p;
            __nv_bfloat16 hi = __float2bfloat16(v);
            g_ahi[idx] = hi;
            g_alo[idx] = __float2bfloat16(v - __bfloat162float(hi));
        }
}

// ---------------- launch ----------------
extern "C" void kernel_launch(void* const* d_in, const int* in_sizes, int n_in,
                              void* d_out, int out_size) {
    const float* feat = (const float*)d_in[0];
    const float* W0 = (const float*)d_in[1];
    const float* al0 = (const float*)d_in[2];
    const float* ar0 = (const float*)d_in[3];
    const float* b0 = (const float*)d_in[4];
    const float* W1 = (const float*)d_in[5];
    const float* al1 = (const float*)d_in[6];
    const float* ar1 = (const float*)d_in[7];
    const float* b1 = (const float*)d_in[8];
    const float* W2 = (const float*)d_in[9];
    const float* al2 = (const float*)d_in[10];
    const float* ar2 = (const float*)d_in[11];
    const float* b2 = (const float*)d_in[12];
    const int* src = (const int*)d_in[13];
    const int* dst = (const int*)d_in[14];
    float* out = (float*)d_out;

    float *p_z, *p_h, *p_bias2;
    __nv_bfloat16 *p_ahi, *p_alo, *p_bthi, *p_btlo;
    cudaGetSymbolAddress((void**)&p_z, g_z);
    cudaGetSymbolAddress((void**)&p_h, g_h);
    cudaGetSymbolAddress((void**)&p_bias2, g_bias2);
    cudaGetSymbolAddress((void**)&p_ahi, g_ahi);
    cudaGetSymbolAddress((void**)&p_alo, g_alo);
    cudaGetSymbolAddress((void**)&p_bthi, g_bthi);
    cudaGetSymbolAddress((void**)&p_btlo, g_btlo);

    cudaFuncSetAttribute(k_gemm_mma, cudaFuncAttributeMaxDynamicSharedMemorySize, GEMM_SMEM);

    const int TB = 256;
    int eb = (NE + TB - 1) / TB;
    int nwb = (NN * 32 + TB - 1) / TB;   // one warp per node
    dim3 ggrid(2, (NN + 127) / 128);

    // CSR build + weight precompute
    k_zero_deg<<<(NN + TB - 1) / TB, TB>>>();
    k_count<<<eb, TB>>>(dst);
    k_prep_scores<<<8, 256>>>(W2, al2, ar2);
    k_bias2<<<1, 256>>>(b2);
    k_scan<<<1, 1024>>>();
    k_fill<<<eb, TB>>>(src, dst);

    // ---- layer 0: 128 -> 4x64, ELU
    k_splitA<<<(NN * 128 + TB - 1) / TB, TB>>>(feat, p_ahi, p_alo, NN * 128);
    k_splitWt<<<(128 * 256 + TB - 1) / TB, TB>>>(W0, 128, 256);
    k_gemm_mma<<<ggrid, 256, GEMM_SMEM>>>(p_ahi, p_alo, p_bthi, p_btlo, p_z, NN, 256, 128,
                                          1.f, nullptr);
    k_scores<<<nwb, TB>>>(p_z, al0, ar0);
    k_stats<<<nwb, TB>>>();
    k_agg_mid<<<nwb, TB>>>(p_z, b0, p_h);

    // ---- layer 1: 256 -> 4x64, ELU
    k_splitWt<<<(256 * 256 + TB - 1) / TB, TB>>>(W1, 256, 256);
    k_gemm_mma<<<ggrid, 256, GEMM_SMEM>>>(p_ahi, p_alo, p_bthi, p_btlo, p_z, NN, 256, 256,
                                          1.f, nullptr);
    k_scores<<<nwb, TB>>>(p_z, al1, ar1);
    k_stats<<<nwb, TB>>>();
    k_agg_mid<<<nwb, TB>>>(p_z, b1, p_h);

    // ---- layer 2: scores from h1, aggregate h1, single GEMM K=1024
    k_scores2<<<nwb, TB>>>(p_h);
    k_stats<<<nwb, TB>>>();
    k_agg2<<<nwb, TB>>>(p_h);
    k_splitW2<<<(256 * 1024 + TB - 1) / TB, TB>>>(W2);
    k_gemm_mma<<<ggrid, 256, GEMM_SMEM>>>(p_ahi, p_alo, p_bthi, p_btlo, out, NN, 256, 1024,
                                          0.25f, p_bias2);
}

// round 7
// speedup vs baseline: 1.4267x; 1.4267x over previous
#include <cuda_runtime.h>
#include <cuda_bf16.h>
#include <math.h>
#include <float.h>
#include <stdint.h>

#define NN 50000
#define NE 800000
#define NHEAD 4

// ---------------- scratch (device globals; no allocation allowed) ----------------
__device__ float g_z[(size_t)NN * 256];    // GEMM0/1 output (projected feats, fp32)
__device__ float g_h[(size_t)NN * 256];    // hidden activations (fp32, for scores/agg)
__device__ __nv_bfloat16 g_ahi[(size_t)NN * 1024];  // GEMM A operand, bf16 high part
__device__ __nv_bfloat16 g_alo[(size_t)NN * 1024];  // GEMM A operand, bf16 low part
__device__ __nv_bfloat16 g_bthi[256 * 1024];        // GEMM B operand [N,K] K-major, hi
__device__ __nv_bfloat16 g_btlo[256 * 1024];        // GEMM B operand [N,K] K-major, lo
__device__ float g_el[NN * NHEAD];
__device__ float g_er[NN * NHEAD];
__device__ float g_alpha[(size_t)NE * NHEAD];  // normalized attention, dst-sorted order
__device__ int   g_ss[NE];                     // src node per sorted edge
__device__ int   g_deg[NN];
__device__ int   g_cur[NN];
__device__ int   g_off[NN + 1];
__device__ float g_wl2[NHEAD * 256];
__device__ float g_wr2[NHEAD * 256];
__device__ float g_bias2[256];

// ================= warp-MMA helpers (sm_80+ PTX, works under compute_103) =================
__device__ __forceinline__ uint32_t smem_u32(const void* p) {
    uint32_t a;
    asm("{ .reg .u64 t; cvta.to.shared.u64 t, %1; cvt.u32.u64 %0, t; }" : "=r"(a) : "l"(p));
    return a;
}
#define LDM4(r0, r1, r2, r3, addr) \
    asm volatile("ldmatrix.sync.aligned.m8n8.x4.shared.b16 {%0,%1,%2,%3}, [%4];" \
                 : "=r"(r0), "=r"(r1), "=r"(r2), "=r"(r3) : "r"(addr))
#define MMA16816(d, a, b) \
    asm volatile("mma.sync.aligned.m16n8k16.row.col.f32.bf16.bf16.f32 " \
                 "{%0,%1,%2,%3}, {%4,%5,%6,%7}, {%8,%9}, {%0,%1,%2,%3};" \
                 : "+f"((d)[0]), "+f"((d)[1]), "+f"((d)[2]), "+f"((d)[3]) \
                 : "r"((a)[0]), "r"((a)[1]), "r"((a)[2]), "r"((a)[3]), \
                   "r"((b)[0]), "r"((b)[1]))

// ================= split-bf16 tensor-core GEMM, register-prefetch double buffer =================
// C[M,N] = scale*(A@B^T) + bias.  A=[M,K] K-major bf16 hi/lo, B=[N,K] K-major bf16 hi/lo.
// Block 128x128, BK=32, 8 warps of 64x32. N multiple of 128, K multiple of 32, M guarded.
// smem stays 40KB (static) so occupancy matches the proven R5 kernel; global loads for
// stage s+1 are issued into registers before the compute of stage s.
#define GBM 128
#define GBN 128
#define GBK 32
#define GPAD 40

__global__ void __launch_bounds__(256)
k_gemm_mma(const __nv_bfloat16* __restrict__ Ahi, const __nv_bfloat16* __restrict__ Alo,
           const __nv_bfloat16* __restrict__ Bhi, const __nv_bfloat16* __restrict__ Blo,
           float* __restrict__ C, int M, int N, int K,
           float scale, const float* __restrict__ bias) {
    __shared__ __nv_bfloat16 sAhi[GBM * GPAD];
    __shared__ __nv_bfloat16 sAlo[GBM * GPAD];
    __shared__ __nv_bfloat16 sBhi[GBN * GPAD];
    __shared__ __nv_bfloat16 sBlo[GBN * GPAD];

    int tid = threadIdx.x;
    int lane = tid & 31;
    int wid = tid >> 5;
    int wm = wid >> 2;   // 0..1 -> 64-row block
    int wn = wid & 3;    // 0..3 -> 32-col block
    int bm = blockIdx.y * GBM;
    int bn = blockIdx.x * GBN;

    uint32_t bAhi = smem_u32(sAhi), bAlo = smem_u32(sAlo);
    uint32_t bBhi = smem_u32(sBhi), bBlo = smem_u32(sBlo);

    // per-thread load slots: 2048 uint4 chunks / 256 threads = 8 slots
    const __nv_bfloat16* gptr[8];
    __nv_bfloat16* sptr[8];
    bool valid[8];
#pragma unroll
    for (int t = 0; t < 8; t++) {
        int idx = tid + t * 256;
        int tile = idx >> 9;        // 0:Ahi 1:Alo 2:Bhi 3:Blo
        int u = idx & 511;
        int row = u >> 2;
        int ch = u & 3;
        __nv_bfloat16* sbase = (tile == 0) ? sAhi : (tile == 1) ? sAlo : (tile == 2) ? sBhi : sBlo;
        sptr[t] = sbase + row * GPAD + ch * 8;
        if (tile < 2) {
            int gm = bm + row;
            valid[t] = (gm < M);
            const __nv_bfloat16* gb = (tile == 0) ? Ahi : Alo;
            gptr[t] = gb + (size_t)(valid[t] ? gm : 0) * K + ch * 8;
        } else {
            int gn = bn + row;
            valid[t] = true;
            const __nv_bfloat16* gb = (tile == 2) ? Bhi : Blo;
            gptr[t] = gb + (size_t)gn * K + ch * 8;
        }
    }

    float acc[4][4][4];
#pragma unroll
    for (int i = 0; i < 4; i++)
#pragma unroll
        for (int j = 0; j < 4; j++)
#pragma unroll
            for (int r = 0; r < 4; r++) acc[i][j][r] = 0.f;

    int lrow = lane & 15;            // ldmatrix row within 16
    int lcol = (lane >> 4) * 8;      // ldmatrix col-half

    int nst = K / GBK;
    uint4 pre[8];
    // prologue: stage 0 -> registers
#pragma unroll
    for (int t = 0; t < 8; t++)
        pre[t] = valid[t] ? *reinterpret_cast<const uint4*>(gptr[t]) : make_uint4(0, 0, 0, 0);

    for (int s = 0; s < nst; s++) {
        // registers -> smem
#pragma unroll
        for (int t = 0; t < 8; t++) *reinterpret_cast<uint4*>(sptr[t]) = pre[t];
        __syncthreads();

        // issue next stage's global loads before compute
        if (s + 1 < nst) {
            int k0 = (s + 1) * GBK;
#pragma unroll
            for (int t = 0; t < 8; t++)
                pre[t] = valid[t] ? *reinterpret_cast<const uint4*>(gptr[t] + k0)
                                  : make_uint4(0, 0, 0, 0);
        }

#pragma unroll
        for (int kk = 0; kk < 2; kk++) {
            int kb = kk * 16;
            uint32_t ahi[4][4], alo[4][4];
#pragma unroll
            for (int i = 0; i < 4; i++) {
                uint32_t off = (uint32_t)((wm * 64 + i * 16 + lrow) * GPAD + kb + lcol) * 2;
                LDM4(ahi[i][0], ahi[i][1], ahi[i][2], ahi[i][3], bAhi + off);
                LDM4(alo[i][0], alo[i][1], alo[i][2], alo[i][3], bAlo + off);
            }
            uint32_t bhi[4][2], blo[4][2];
#pragma unroll
            for (int j = 0; j < 2; j++) {
                uint32_t off = (uint32_t)((wn * 32 + j * 16 + lrow) * GPAD + kb + lcol) * 2;
                uint32_t r0, r1, r2, r3;
                LDM4(r0, r1, r2, r3, bBhi + off);
                bhi[2 * j][0] = r0; bhi[2 * j][1] = r2;
                bhi[2 * j + 1][0] = r1; bhi[2 * j + 1][1] = r3;
                LDM4(r0, r1, r2, r3, bBlo + off);
                blo[2 * j][0] = r0; blo[2 * j][1] = r2;
                blo[2 * j + 1][0] = r1; blo[2 * j + 1][1] = r3;
            }
#pragma unroll
            for (int i = 0; i < 4; i++)
#pragma unroll
                for (int n = 0; n < 4; n++) {
                    MMA16816(acc[i][n], ahi[i], bhi[n]);
                    MMA16816(acc[i][n], ahi[i], blo[n]);
                    MMA16816(acc[i][n], alo[i], bhi[n]);
                }
        }
        __syncthreads();
    }

    // ---- epilogue: documented m16n8 acc mapping, guarded direct global stores
    int g = lane >> 2, tg = lane & 3;
#pragma unroll
    for (int mi = 0; mi < 4; mi++) {
        int r0 = bm + wm * 64 + mi * 16 + g;
        int r1 = r0 + 8;
#pragma unroll
        for (int ni = 0; ni < 4; ni++) {
            int c = bn + wn * 32 + ni * 8 + tg * 2;
            float b0 = 0.f, b1 = 0.f;
            if (bias) { b0 = bias[c]; b1 = bias[c + 1]; }
            if (r0 < M) {
                float2 v = make_float2(scale * acc[mi][ni][0] + b0,
                                       scale * acc[mi][ni][1] + b1);
                *reinterpret_cast<float2*>(&C[(size_t)r0 * N + c]) = v;
            }
            if (r1 < M) {
                float2 v = make_float2(scale * acc[mi][ni][2] + b0,
                                       scale * acc[mi][ni][3] + b1);
                *reinterpret_cast<float2*>(&C[(size_t)r1 * N + c]) = v;
            }
        }
    }
}

// ================= bf16 split conversions =================
__global__ void k_splitA(const float* __restrict__ in, __nv_bfloat16* __restrict__ hi,
                         __nv_bfloat16* __restrict__ lo, int count) {
    int i = blockIdx.x * blockDim.x + threadIdx.x;
    if (i >= count) return;
    float f = in[i];
    __nv_bfloat16 h = __float2bfloat16(f);
    hi[i] = h;
    lo[i] = __float2bfloat16(f - __bfloat162float(h));
}

// transpose W[K,N] -> Wt[N,K] with split
__global__ void k_splitWt(const float* __restrict__ W, int K, int N) {
    int t = blockIdx.x * blockDim.x + threadIdx.x;
    if (t >= K * N) return;
    int n = t / K, k = t % K;
    float f = W[(size_t)k * N + n];
    __nv_bfloat16 h = __float2bfloat16(f);
    g_bthi[t] = h;
    g_btlo[t] = __float2bfloat16(f - __bfloat162float(h));
}

// layer2 B: Bt[c][h*256+kk] = W2[kk*1024 + h*256 + c], output [256,1024]
__global__ void k_splitW2(const float* __restrict__ W2) {
    int t = blockIdx.x * blockDim.x + threadIdx.x;   // 0..262143
    if (t >= 256 * 1024) return;
    int c = t >> 10;
    int r = t & 1023;
    int h = r >> 8, kk = r & 255;
    float f = W2[(size_t)kk * 1024 + h * 256 + c];
    __nv_bfloat16 hh = __float2bfloat16(f);
    g_bthi[t] = hh;
    g_btlo[t] = __float2bfloat16(f - __bfloat162float(hh));
}

// ---------------- CSR build (by destination) ----------------
__global__ void k_zero_deg() {
    int i = blockIdx.x * blockDim.x + threadIdx.x;
    if (i < NN) g_deg[i] = 0;
}
__global__ void k_count(const int* __restrict__ dst) {
    int i = blockIdx.x * blockDim.x + threadIdx.x;
    if (i < NE) atomicAdd(&g_deg[dst[i]], 1);
}
__global__ void k_scan() {
    __shared__ int sh[1024];
    __shared__ int carry;
    if (threadIdx.x == 0) carry = 0;
    __syncthreads();
    for (int base = 0; base < NN; base += 1024) {
        int i = base + threadIdx.x;
        int v = (i < NN) ? g_deg[i] : 0;
        sh[threadIdx.x] = v;
        __syncthreads();
        for (int o = 1; o < 1024; o <<= 1) {
            int t = (threadIdx.x >= o) ? sh[threadIdx.x - o] : 0;
            __syncthreads();
            sh[threadIdx.x] += t;
            __syncthreads();
        }
        if (i < NN) {
            int excl = carry + sh[threadIdx.x] - v;
            g_off[i] = excl;
            g_cur[i] = excl;
        }
        __syncthreads();
        if (threadIdx.x == 0) carry += sh[1023];
        __syncthreads();
    }
    if (threadIdx.x == 0) g_off[NN] = carry;
}
// fill: writes src id directly into dst-sorted slot
__global__ void k_fill(const int* __restrict__ src, const int* __restrict__ dst) {
    int i = blockIdx.x * blockDim.x + threadIdx.x;
    if (i < NE) {
        int d = dst[i];
        int p = atomicAdd(&g_cur[d], 1);
        g_ss[p] = src[i];
    }
}

// ---------------- layer-2 precompute ----------------
__global__ void k_prep_scores(const float* __restrict__ W2, const float* __restrict__ al2,
                              const float* __restrict__ ar2) {
    int t = blockIdx.x * blockDim.x + threadIdx.x;
    int which = t >> 10;
    int hk = t & 1023;
    int h = hk >> 8, k = hk & 255;
    const float* a = (which == 0 ? al2 : ar2) + h * 256;
    const float* wrow = W2 + (size_t)k * 1024 + h * 256;
    float s = 0.f;
#pragma unroll 8
    for (int c = 0; c < 256; c++) s += wrow[c] * a[c];
    if (which == 0) g_wl2[hk] = s;
    else            g_wr2[hk] = s;
}
__global__ void k_bias2(const float* __restrict__ b2) {
    int c = threadIdx.x;
    g_bias2[c] = 0.25f * (b2[c] + b2[256 + c] + b2[512 + c] + b2[768 + c]);
}

// ---------------- per-node attention scores (layers 0/1, F=64) ----------------
__global__ void k_scores(const float* __restrict__ z, const float* __restrict__ al,
                         const float* __restrict__ ar) {
    int gw = (blockIdx.x * blockDim.x + threadIdx.x) >> 5;
    int lane = threadIdx.x & 31;
    if (gw >= NN) return;
    const float* row = z + (size_t)gw * 256;
    float accl[NHEAD], accr[NHEAD];
#pragma unroll
    for (int h = 0; h < NHEAD; h++) { accl[h] = 0.f; accr[h] = 0.f; }
#pragma unroll
    for (int i = 0; i < 8; i++) {
        int j = lane + 32 * i;
        float v = row[j];
        int h = i >> 1;
        accl[h] += v * al[j];
        accr[h] += v * ar[j];
    }
#pragma unroll
    for (int h = 0; h < NHEAD; h++) {
        float l = accl[h], r = accr[h];
#pragma unroll
        for (int o = 16; o > 0; o >>= 1) {
            l += __shfl_xor_sync(0xffffffffu, l, o);
            r += __shfl_xor_sync(0xffffffffu, r, o);
        }
        if (lane == 0) {
            g_el[gw * NHEAD + h] = l;
            g_er[gw * NHEAD + h] = r;
        }
    }
}

// ---------------- layer-2 scores directly from h1 ----------------
__global__ void k_scores2(const float* __restrict__ h1) {
    int gw = (blockIdx.x * blockDim.x + threadIdx.x) >> 5;
    int lane = threadIdx.x & 31;
    if (gw >= NN) return;
    const float* row = h1 + (size_t)gw * 256;
    float accl[NHEAD], accr[NHEAD];
#pragma unroll
    for (int h = 0; h < NHEAD; h++) { accl[h] = 0.f; accr[h] = 0.f; }
#pragma unroll
    for (int i = 0; i < 8; i++) {
        int j = lane + 32 * i;
        float v = row[j];
#pragma unroll
        for (int h = 0; h < NHEAD; h++) {
            accl[h] += v * g_wl2[h * 256 + j];
            accr[h] += v * g_wr2[h * 256 + j];
        }
    }
#pragma unroll
    for (int h = 0; h < NHEAD; h++) {
        float l = accl[h], r = accr[h];
#pragma unroll
        for (int o = 16; o > 0; o >>= 1) {
            l += __shfl_xor_sync(0xffffffffu, l, o);
            r += __shfl_xor_sync(0xffffffffu, r, o);
        }
        if (lane == 0) {
            g_el[gw * NHEAD + h] = l;
            g_er[gw * NHEAD + h] = r;
        }
    }
}

// ---------------- per-node segment softmax (scores computed on the fly) ----------------
__device__ __forceinline__ float4 edge_score(int s, const float4& er) {
    float4 l = *reinterpret_cast<const float4*>(&g_el[s * 4]);
    float4 v;
    float x;
    x = l.x + er.x; v.x = x > 0.f ? x : 0.2f * x;
    x = l.y + er.y; v.y = x > 0.f ? x : 0.2f * x;
    x = l.z + er.z; v.z = x > 0.f ? x : 0.2f * x;
    x = l.w + er.w; v.w = x > 0.f ? x : 0.2f * x;
    return v;
}

__global__ void k_stats() {
    int n = (blockIdx.x * blockDim.x + threadIdx.x) >> 5;
    int lane = threadIdx.x & 31;
    if (n >= NN) return;
    int j0 = g_off[n], j1 = g_off[n + 1];
    float4 er = *reinterpret_cast<const float4*>(&g_er[n * 4]);
    float m[NHEAD], s[NHEAD];
#pragma unroll
    for (int h = 0; h < NHEAD; h++) { m[h] = -FLT_MAX; s[h] = 0.f; }
    for (int j = j0 + lane; j < j1; j += 32) {
        float4 e4 = edge_score(g_ss[j], er);
        float ev[4] = {e4.x, e4.y, e4.z, e4.w};
#pragma unroll
        for (int h = 0; h < NHEAD; h++) {
            float nm = fmaxf(m[h], ev[h]);
            s[h] = s[h] * __expf(m[h] - nm) + __expf(ev[h] - nm);
            m[h] = nm;
        }
    }
#pragma unroll
    for (int h = 0; h < NHEAD; h++) {
#pragma unroll
        for (int o = 16; o > 0; o >>= 1) {
            float om = __shfl_xor_sync(0xffffffffu, m[h], o);
            float os = __shfl_xor_sync(0xffffffffu, s[h], o);
            float nm = fmaxf(m[h], om);
            s[h] = s[h] * __expf(m[h] - nm) + os * __expf(om - nm);
            m[h] = nm;
        }
    }
    float inv[NHEAD];
#pragma unroll
    for (int h = 0; h < NHEAD; h++) inv[h] = 1.f / fmaxf(s[h], 1e-9f);
    for (int j = j0 + lane; j < j1; j += 32) {
        float4 e4 = edge_score(g_ss[j], er);
        float4 a;
        a.x = __expf(e4.x - m[0]) * inv[0];
        a.y = __expf(e4.y - m[1]) * inv[1];
        a.z = __expf(e4.z - m[2]) * inv[2];
        a.w = __expf(e4.w - m[3]) * inv[3];
        *reinterpret_cast<float4*>(&g_alpha[(size_t)j * 4]) = a;
    }
}

// ---------------- hidden-layer aggregation: warp per node, all 4 heads ----------------
// writes fp32 h and bf16 hi/lo split (as next GEMM's A operand, K=256)
__global__ void k_agg_mid(const float* __restrict__ z, const float* __restrict__ bias,
                          float* __restrict__ hout) {
    int n = (blockIdx.x * blockDim.x + threadIdx.x) >> 5;
    int lane = threadIdx.x & 31;
    if (n >= NN) return;
    int j0 = g_off[n], j1 = g_off[n + 1];
    float acc[NHEAD][2];
#pragma unroll
    for (int h = 0; h < NHEAD; h++) { acc[h][0] = 0.f; acc[h][1] = 0.f; }
    for (int j = j0; j < j1; j++) {
        float4 a = *reinterpret_cast<const float4*>(&g_alpha[(size_t)j * 4]);
        const float* zr = z + (size_t)g_ss[j] * 256;
        float av[4] = {a.x, a.y, a.z, a.w};
#pragma unroll
        for (int h = 0; h < NHEAD; h++) {
            acc[h][0] += av[h] * zr[h * 64 + lane];
            acc[h][1] += av[h] * zr[h * 64 + lane + 32];
        }
    }
#pragma unroll
    for (int h = 0; h < NHEAD; h++) {
        float v0 = acc[h][0] + bias[h * 64 + lane];
        float v1 = acc[h][1] + bias[h * 64 + lane + 32];
        v0 = v0 > 0.f ? v0 : (__expf(v0) - 1.f);
        v1 = v1 > 0.f ? v1 : (__expf(v1) - 1.f);
        size_t i0 = (size_t)n * 256 + h * 64 + lane;
        hout[i0] = v0;
        hout[i0 + 32] = v1;
        __nv_bfloat16 h0 = __float2bfloat16(v0);
        __nv_bfloat16 h1b = __float2bfloat16(v1);
        g_ahi[i0] = h0;
        g_ahi[i0 + 32] = h1b;
        g_alo[i0] = __float2bfloat16(v0 - __bfloat162float(h0));
        g_alo[i0 + 32] = __float2bfloat16(v1 - __bfloat162float(h1b));
    }
}

// ---------------- layer-2 aggregation of h1 into bf16 split A [N,1024] ----------------
__global__ void k_agg2(const float* __restrict__ h1) {
    int n = (blockIdx.x * blockDim.x + threadIdx.x) >> 5;
    int lane = threadIdx.x & 31;
    if (n >= NN) return;
    int j0 = g_off[n], j1 = g_off[n + 1];
    float acc[NHEAD][8];
#pragma unroll
    for (int h = 0; h < NHEAD; h++)
#pragma unroll
        for (int p = 0; p < 8; p++) acc[h][p] = 0.f;
    for (int j = j0; j < j1; j++) {
        float4 a = *reinterpret_cast<const float4*>(&g_alpha[(size_t)j * 4]);
        const float* hr = h1 + (size_t)g_ss[j] * 256;
#pragma unroll
        for (int p = 0; p < 8; p++) {
            float v = hr[lane + 32 * p];
            acc[0][p] += a.x * v;
            acc[1][p] += a.y * v;
            acc[2][p] += a.z * v;
            acc[3][p] += a.w * v;
        }
    }
    size_t base = (size_t)n * 1024;
#pragma unroll
    for (int h = 0; h < NHEAD; h++)
#pragma unroll
        for (int p = 0; p < 8; p++) {
            float v = acc[h][p];
            size_t idx = base + h * 256 + lane + 32 * p;
            __nv_bfloat16 hi = __float2bfloat16(v);
            g_ahi[idx] = hi;
            g_alo[idx] = __float2bfloat16(v - __bfloat162float(hi));
        }
}

// ---------------- launch ----------------
extern "C" void kernel_launch(void* const* d_in, const int* in_sizes, int n_in,
                              void* d_out, int out_size) {
    const float* feat = (const float*)d_in[0];
    const float* W0 = (const float*)d_in[1];
    const float* al0 = (const float*)d_in[2];
    const float* ar0 = (const float*)d_in[3];
    const float* b0 = (const float*)d_in[4];
    const float* W1 = (const float*)d_in[5];
    const float* al1 = (const float*)d_in[6];
    const float* ar1 = (const float*)d_in[7];
    const float* b1 = (const float*)d_in[8];
    const float* W2 = (const float*)d_in[9];
    const float* al2 = (const float*)d_in[10];
    const float* ar2 = (const float*)d_in[11];
    const float* b2 = (const float*)d_in[12];
    const int* src = (const int*)d_in[13];
    const int* dst = (const int*)d_in[14];
    float* out = (float*)d_out;

    float *p_z, *p_h, *p_bias2;
    __nv_bfloat16 *p_ahi, *p_alo, *p_bthi, *p_btlo;
    cudaGetSymbolAddress((void**)&p_z, g_z);
    cudaGetSymbolAddress((void**)&p_h, g_h);
    cudaGetSymbolAddress((void**)&p_bias2, g_bias2);
    cudaGetSymbolAddress((void**)&p_ahi, g_ahi);
    cudaGetSymbolAddress((void**)&p_alo, g_alo);
    cudaGetSymbolAddress((void**)&p_bthi, g_bthi);
    cudaGetSymbolAddress((void**)&p_btlo, g_btlo);

    const int TB = 256;
    int eb = (NE + TB - 1) / TB;
    int nwb = (NN * 32 + TB - 1) / TB;   // one warp per node
    dim3 ggrid(2, (NN + 127) / 128);

    // CSR build + weight precompute
    k_zero_deg<<<(NN + TB - 1) / TB, TB>>>();
    k_count<<<eb, TB>>>(dst);
    k_prep_scores<<<8, 256>>>(W2, al2, ar2);
    k_bias2<<<1, 256>>>(b2);
    k_scan<<<1, 1024>>>();
    k_fill<<<eb, TB>>>(src, dst);

    // ---- layer 0: 128 -> 4x64, ELU
    k_splitA<<<(NN * 128 + TB - 1) / TB, TB>>>(feat, p_ahi, p_alo, NN * 128);
    k_splitWt<<<(128 * 256 + TB - 1) / TB, TB>>>(W0, 128, 256);
    k_gemm_mma<<<ggrid, 256>>>(p_ahi, p_alo, p_bthi, p_btlo, p_z, NN, 256, 128, 1.f, nullptr);
    k_scores<<<nwb, TB>>>(p_z, al0, ar0);
    k_stats<<<nwb, TB>>>();
    k_agg_mid<<<nwb, TB>>>(p_z, b0, p_h);

    // ---- layer 1: 256 -> 4x64, ELU
    k_splitWt<<<(256 * 256 + TB - 1) / TB, TB>>>(W1, 256, 256);
    k_gemm_mma<<<ggrid, 256>>>(p_ahi, p_alo, p_bthi, p_btlo, p_z, NN, 256, 256, 1.f, nullptr);
    k_scores<<<nwb, TB>>>(p_z, al1, ar1);
    k_stats<<<nwb, TB>>>();
    k_agg_mid<<<nwb, TB>>>(p_z, b1, p_h);

    // ---- layer 2: scores from h1, aggregate h1, single GEMM K=1024
    k_scores2<<<nwb, TB>>>(p_h);
    k_stats<<<nwb, TB>>>();
    k_agg2<<<nwb, TB>>>(p_h);
    k_splitW2<<<(256 * 1024 + TB - 1) / TB, TB>>>(W2);
    k_gemm_mma<<<ggrid, 256>>>(p_ahi, p_alo, p_bthi, p_btlo, out, NN, 256, 1024, 0.25f, p_bias2);
}